// round 17
// baseline (speedup 1.0000x reference)
#include <cuda_runtime.h>
#include <cstdint>

#define BATCH    256
#define IN_CAPS  1152
#define NUM_CAPS 10
#define DIM_VEC  16
#define EPS 1e-7f
#define NTH      320                  // 32 lanes x 10 c-warps

// ---- pass1/2 tiling (NB=2) ----
#define ITILE    8
#define NBLK_I   (IN_CAPS / ITILE)    // 144
#define B_TILE   64
#define NBLK_B   (BATCH / B_TILE)     // 4
#define XR       68                   // x row stride (64 + 4 pad; conflict-free)
#define WS_F   (ITILE * NUM_CAPS * 8 * DIM_VEC)  // 10240 : [ii][c][e][d16]
#define XS_F   (B_TILE * XR)                     // 4352  : [bb64][j]
#define VV_U   (NUM_CAPS * 8 * 32)               // 2560 ull : vvB [c][p][bb32]
#define EX_F   (2 * B_TILE * 12)                 // 1536  : [slot][bb64][c] stride 12
#define SMEM_BYTES ((WS_F + XS_F + EX_F) * 4 + VV_U * 8)   // 84992 B

// ---- pass0 tiling (NB=4, champion) ----
#define ITILE0   8
#define NBLK_I0  (IN_CAPS / ITILE0)   // 144
#define B_TILE0  128
#define NBLK_B0  (BATCH / B_TILE0)    // 2
#define XR0      68
#define WS0_F  (ITILE0 * NUM_CAPS * 8 * DIM_VEC) // 10240
#define XS0_F  (B_TILE0 * XR0)                   // 8704
#define CF0_F  (ITILE0 * NUM_CAPS)               // 80
#define SMEM0_BYTES ((WS0_F + XS0_F + CF0_F) * 4)  // 76096 B

__device__ float g_sbuf[3][BATCH * NUM_CAPS * DIM_VEC];   // zero-init; final re-zeros
__device__ float g_blog[IN_CAPS * NUM_CAPS * BATCH];      // [i][c][b] : stores b1+bias

using ull = unsigned long long;
__device__ __forceinline__ ull pack2(float lo, float hi) {
    ull r; asm("mov.b64 %0,{%1,%2};" : "=l"(r) : "f"(lo), "f"(hi)); return r;
}
__device__ __forceinline__ ull dup2(float v) {
    ull r; asm("mov.b64 %0,{%1,%1};" : "=l"(r) : "f"(v)); return r;
}
__device__ __forceinline__ void unpack2(ull v, float& lo, float& hi) {
    asm("mov.b64 {%0,%1},%2;" : "=f"(lo), "=f"(hi) : "l"(v));
}
__device__ __forceinline__ ull ffma2(ull a, ull b, ull c) {
    ull d; asm("fma.rn.f32x2 %0,%1,%2,%3;" : "=l"(d) : "l"(a), "l"(b), "l"(c)); return d;
}

// Common W-tile stage: global [i][c][d][e] (float4 = d,e0..3) -> ws[ii][c][e][d]
__device__ __forceinline__ void stage_w(float* ws, const float* W, int i0, int tid, int itile)
{
    const float4* Wg = (const float4*)(W + (size_t)i0 * NUM_CAPS * DIM_VEC * 8);
    #pragma unroll 2
    for (int k = tid; k < itile * NUM_CAPS * DIM_VEC * 2; k += NTH) {
        float4 w4 = Wg[k];                    // coalesced LDG.128
        int ii = k / (NUM_CAPS * DIM_VEC * 2);
        int r  = k - ii * (NUM_CAPS * DIM_VEC * 2);
        int cc = r >> 5;
        int d  = (r >> 1) & 15;
        int e0 = (r & 1) * 4;
        float* dst = ws + (((ii * NUM_CAPS + cc) * 8) + e0) * DIM_VEC + d;
        dst[0 * DIM_VEC] = w4.x;
        dst[1 * DIM_VEC] = w4.y;
        dst[2 * DIM_VEC] = w4.z;
        dst[3 * DIM_VEC] = w4.w;
    }
}

// PASS 0: s0 += softmax_c(bias) * u_hat, NB=4 (coef folded into x; no uh regs)
__global__ void __launch_bounds__(NTH, 2)
pass0_kernel(const float* __restrict__ x,
             const float* __restrict__ W,
             const float* __restrict__ bias)
{
    extern __shared__ __align__(16) float sh[];
    float* ws  = sh;
    float* xs  = sh + WS0_F;
    float* cfs = sh + WS0_F + XS0_F;

    const int tid = threadIdx.x;
    const int bb  = tid & 31;
    const int c   = tid >> 5;
    const int i0  = blockIdx.x * ITILE0;
    const int b0  = blockIdx.y * B_TILE0;

    stage_w(ws, W, i0, tid, ITILE0);
    for (int t = tid; t < B_TILE0 * ITILE0 * 8; t += NTH) {
        int lb = t >> 6;
        int j  = t & 63;
        xs[lb * XR0 + j] = x[(size_t)(b0 + lb) * (IN_CAPS * 8) + i0 * 8 + j];
    }
    if (tid < ITILE0) {
        const float* bp = bias + (i0 + tid) * NUM_CAPS;
        float ex[NUM_CAPS]; float den = 0.f;
        #pragma unroll
        for (int k = 0; k < NUM_CAPS; k++) { ex[k] = __expf(bp[k]); den += ex[k]; }
        float inv = __frcp_rn(den);
        #pragma unroll
        for (int k = 0; k < NUM_CAPS; k++) cfs[tid * NUM_CAPS + k] = ex[k] * inv;
    }

    cudaTriggerProgrammaticLaunchCompletion();
    __syncthreads();

    ull sacc[4][8];
    #pragma unroll
    for (int nb = 0; nb < 4; nb++)
        #pragma unroll
        for (int p = 0; p < 8; p++) sacc[nb][p] = 0ull;

    #pragma unroll 1
    for (int ii = 0; ii < ITILE0; ii++) {
        const float cf = cfs[ii * NUM_CAPS + c];
        const ulonglong2* wp = (const ulonglong2*)(ws + ((ii * NUM_CAPS + c) * 8) * DIM_VEC);

        #pragma unroll
        for (int half = 0; half < 2; half++) {
            float xv[4][4];
            #pragma unroll
            for (int nb = 0; nb < 4; nb++) {
                float4 x4 = *(const float4*)(xs + (bb + 32 * nb) * XR0 + ii * 8 + half * 4);
                xv[nb][0] = x4.x * cf; xv[nb][1] = x4.y * cf;
                xv[nb][2] = x4.z * cf; xv[nb][3] = x4.w * cf;
            }
            #pragma unroll
            for (int e = 0; e < 4; e++) {
                const ulonglong2* wq = wp + (half * 4 + e) * 4;
                ulonglong2 w0 = wq[0];
                ulonglong2 w1 = wq[1];
                ulonglong2 w2 = wq[2];
                ulonglong2 w3 = wq[3];
                #pragma unroll
                for (int nb = 0; nb < 4; nb++) {
                    ull xd = dup2(xv[nb][e]);
                    sacc[nb][0] = ffma2(w0.x, xd, sacc[nb][0]);
                    sacc[nb][1] = ffma2(w0.y, xd, sacc[nb][1]);
                    sacc[nb][2] = ffma2(w1.x, xd, sacc[nb][2]);
                    sacc[nb][3] = ffma2(w1.y, xd, sacc[nb][3]);
                    sacc[nb][4] = ffma2(w2.x, xd, sacc[nb][4]);
                    sacc[nb][5] = ffma2(w2.y, xd, sacc[nb][5]);
                    sacc[nb][6] = ffma2(w3.x, xd, sacc[nb][6]);
                    sacc[nb][7] = ffma2(w3.y, xd, sacc[nb][7]);
                }
            }
        }
    }

    cudaGridDependencySynchronize();   // prior replay's final must finish zeroing s0
    float a0, a1, a2, a3;
    #pragma unroll
    for (int nb = 0; nb < 4; nb++) {
        float* sp = g_sbuf[0] + ((b0 + bb + 32 * nb) * NUM_CAPS + c) * DIM_VEC;
        #pragma unroll
        for (int q = 0; q < 4; q++) {
            unpack2(sacc[nb][2 * q], a0, a1); unpack2(sacc[nb][2 * q + 1], a2, a3);
            asm volatile("red.global.add.v4.f32 [%0], {%1,%2,%3,%4};"
                         :: "l"(sp + 4 * q), "f"(a0), "f"(a1), "f"(a2), "f"(a3) : "memory");
        }
    }
}

// PASS 1/2, NB=2: vvA in regs, vvB in shared; vectorized softmax denominator.
// PASS 1: b1 = uh.v1 + 2*bias; blog=b1+bias; s1 += softmax(b1)*u_hat
// PASS 2: b2 = uh.v2 + blog;                 s2 += softmax(b2)*u_hat
template <int PASS>
__global__ void __launch_bounds__(NTH, 2)
pass_kernel(const float* __restrict__ x,
            const float* __restrict__ W,
            const float* __restrict__ bias)
{
    extern __shared__ __align__(16) float sh[];
    float* ws  = sh;                          // [ii][c][e][d16]  40 KB
    float* xs  = sh + WS_F;                   // [bb64][j] stride 68
    float* exs = sh + WS_F + XS_F;            // [2][bb64][12]
    ull*   vvs = (ull*)(exs + EX_F);          // vvB [c][p][bb32]  20 KB

    const int tid = threadIdx.x;
    const int bb  = tid & 31;
    const int c   = tid >> 5;
    const int i0  = blockIdx.x * ITILE;
    const int b0  = blockIdx.y * B_TILE;
    const int bA  = b0 + bb;
    const int bB  = bA + 32;

    stage_w(ws, W, i0, tid, ITILE);
    for (int t = tid; t < B_TILE * ITILE * 8; t += NTH) {
        int lb = t >> 6;
        int j  = t & 63;
        xs[lb * XR + j] = x[(size_t)(b0 + lb) * (IN_CAPS * 8) + i0 * 8 + j];
    }

    cudaTriggerProgrammaticLaunchCompletion();

    // v = squash(s_prev): batch A -> registers, batch B -> shared
    ull vvA[8];
    {
        cudaGridDependencySynchronize();      // predecessor's s-adds visible
        {
            const float4* sp = (const float4*)(g_sbuf[PASS - 1] + (bA * NUM_CAPS + c) * DIM_VEC);
            float4 s4[4]; float sq = 0.f;
            #pragma unroll
            for (int q = 0; q < 4; q++) {
                s4[q] = sp[q];
                sq = fmaf(s4[q].x, s4[q].x, sq); sq = fmaf(s4[q].y, s4[q].y, sq);
                sq = fmaf(s4[q].z, s4[q].z, sq); sq = fmaf(s4[q].w, s4[q].w, sq);
            }
            float scale = sq / (1.f + sq) * rsqrtf(sq + EPS);
            #pragma unroll
            for (int q = 0; q < 4; q++) {
                vvA[2 * q]     = pack2(scale * s4[q].x, scale * s4[q].y);
                vvA[2 * q + 1] = pack2(scale * s4[q].z, scale * s4[q].w);
            }
        }
        {
            const float4* sp = (const float4*)(g_sbuf[PASS - 1] + (bB * NUM_CAPS + c) * DIM_VEC);
            float4 s4[4]; float sq = 0.f;
            #pragma unroll
            for (int q = 0; q < 4; q++) {
                s4[q] = sp[q];
                sq = fmaf(s4[q].x, s4[q].x, sq); sq = fmaf(s4[q].y, s4[q].y, sq);
                sq = fmaf(s4[q].z, s4[q].z, sq); sq = fmaf(s4[q].w, s4[q].w, sq);
            }
            float scale = sq / (1.f + sq) * rsqrtf(sq + EPS);
            ull* vb = vvs + (c * 8) * 32 + bb;
            vb[0 * 32] = pack2(scale * s4[0].x, scale * s4[0].y);
            vb[1 * 32] = pack2(scale * s4[0].z, scale * s4[0].w);
            vb[2 * 32] = pack2(scale * s4[1].x, scale * s4[1].y);
            vb[3 * 32] = pack2(scale * s4[1].z, scale * s4[1].w);
            vb[4 * 32] = pack2(scale * s4[2].x, scale * s4[2].y);
            vb[5 * 32] = pack2(scale * s4[2].z, scale * s4[2].w);
            vb[6 * 32] = pack2(scale * s4[3].x, scale * s4[3].y);
            vb[7 * 32] = pack2(scale * s4[3].z, scale * s4[3].w);
        }
    }
    __syncthreads();

    ull saccA[8], saccB[8];
    #pragma unroll
    for (int p = 0; p < 8; p++) { saccA[p] = 0ull; saccB[p] = 0ull; }

    #pragma unroll 1
    for (int ii = 0; ii < ITILE; ii++) {
        const int i = i0 + ii;
        const int slot = ii & 1;

        // prefetch logit base (PASS1: bias, b-independent -> one load)
        float pfA, pfB;
        if (PASS == 1) {
            pfA = __ldg(&bias[i * NUM_CAPS + c]);
            pfB = pfA;
        } else {
            pfA = __ldg(&g_blog[(i * NUM_CAPS + c) * BATCH + bA]);
            pfB = __ldg(&g_blog[(i * NUM_CAPS + c) * BATCH + bB]);
        }

        // u_hat for BOTH batches: 32 W wavefronts feed 128 FFMA2
        ull uhA[8], uhB[8];
        #pragma unroll
        for (int p = 0; p < 8; p++) { uhA[p] = 0ull; uhB[p] = 0ull; }
        const ulonglong2* wp = (const ulonglong2*)(ws + ((ii * NUM_CAPS + c) * 8) * DIM_VEC);
        #pragma unroll
        for (int half = 0; half < 2; half++) {
            float4 xA4 = *(const float4*)(xs + bb * XR + ii * 8 + half * 4);
            float4 xB4 = *(const float4*)(xs + (bb + 32) * XR + ii * 8 + half * 4);
            float xvA[4] = {xA4.x, xA4.y, xA4.z, xA4.w};
            float xvB[4] = {xB4.x, xB4.y, xB4.z, xB4.w};
            #pragma unroll
            for (int e = 0; e < 4; e++) {
                const ulonglong2* wq = wp + (half * 4 + e) * 4;
                ulonglong2 w0 = wq[0];
                ulonglong2 w1 = wq[1];
                ulonglong2 w2 = wq[2];
                ulonglong2 w3 = wq[3];
                ull xdA = dup2(xvA[e]);
                ull xdB = dup2(xvB[e]);
                uhA[0] = ffma2(w0.x, xdA, uhA[0]);
                uhA[1] = ffma2(w0.y, xdA, uhA[1]);
                uhA[2] = ffma2(w1.x, xdA, uhA[2]);
                uhA[3] = ffma2(w1.y, xdA, uhA[3]);
                uhA[4] = ffma2(w2.x, xdA, uhA[4]);
                uhA[5] = ffma2(w2.y, xdA, uhA[5]);
                uhA[6] = ffma2(w3.x, xdA, uhA[6]);
                uhA[7] = ffma2(w3.y, xdA, uhA[7]);
                uhB[0] = ffma2(w0.x, xdB, uhB[0]);
                uhB[1] = ffma2(w0.y, xdB, uhB[1]);
                uhB[2] = ffma2(w1.x, xdB, uhB[2]);
                uhB[3] = ffma2(w1.y, xdB, uhB[3]);
                uhB[4] = ffma2(w2.x, xdB, uhB[4]);
                uhB[5] = ffma2(w2.y, xdB, uhB[5]);
                uhB[6] = ffma2(w3.x, xdB, uhB[6]);
                uhB[7] = ffma2(w3.y, xdB, uhB[7]);
            }
        }

        // agreements: A from register vv, B from shared vv (8 LDS.64)
        ull agA0 = 0ull, agA1 = 0ull, agB0 = 0ull, agB1 = 0ull;
        const ull* vb = vvs + (c * 8) * 32 + bb;
        #pragma unroll
        for (int p = 0; p < 4; p++) {
            agA0 = ffma2(uhA[2 * p],     vvA[2 * p],     agA0);
            agA1 = ffma2(uhA[2 * p + 1], vvA[2 * p + 1], agA1);
            agB0 = ffma2(uhB[2 * p],     vb[(2 * p) * 32],     agB0);
            agB1 = ffma2(uhB[2 * p + 1], vb[(2 * p + 1) * 32], agB1);
        }
        float a0, a1, a2, a3;
        unpack2(agA0, a0, a1); unpack2(agA1, a2, a3);
        float agrA = (a0 + a1) + (a2 + a3);
        unpack2(agB0, a0, a1); unpack2(agB1, a2, a3);
        float agrB = (a0 + a1) + (a2 + a3);

        float bnewA, bnewB;
        if (PASS == 1) {
            bnewA = agrA + 2.f * pfA;
            bnewB = agrB + 2.f * pfA;
            g_blog[(i * NUM_CAPS + c) * BATCH + bA] = bnewA + pfA;   // b1+bias
            g_blog[(i * NUM_CAPS + c) * BATCH + bB] = bnewB + pfA;
        } else {
            bnewA = agrA + pfA;
            bnewB = agrB + pfB;
        }

        float exA = __expf(bnewA);                    // no max-subtract: bounded logits
        float exB = __expf(bnewB);
        float* er = exs + slot * (B_TILE * 12);
        er[bb * 12 + c]        = exA;                 // stride-12: conflict-free STS
        er[(bb + 32) * 12 + c] = exB;
        __syncthreads();                              // ONE barrier per ii (2 slots: WAR-safe)

        // vectorized denominators: 2xLDS.128 + LDS.64 per batch
        float4 eA0 = *(const float4*)(er + bb * 12);
        float4 eA1 = *(const float4*)(er + bb * 12 + 4);
        float2 eA2 = *(const float2*)(er + bb * 12 + 8);
        float denA = ((eA0.x + eA0.y) + (eA0.z + eA0.w))
                   + ((eA1.x + eA1.y) + (eA1.z + eA1.w)) + (eA2.x + eA2.y);
        float4 eB0 = *(const float4*)(er + (bb + 32) * 12);
        float4 eB1 = *(const float4*)(er + (bb + 32) * 12 + 4);
        float2 eB2 = *(const float2*)(er + (bb + 32) * 12 + 8);
        float denB = ((eB0.x + eB0.y) + (eB0.z + eB0.w))
                   + ((eB1.x + eB1.y) + (eB1.z + eB1.w)) + (eB2.x + eB2.y);

        ull cfA = dup2(__fdividef(exA, denA));
        ull cfB = dup2(__fdividef(exB, denB));
        #pragma unroll
        for (int p = 0; p < 8; p++) {
            saccA[p] = ffma2(cfA, uhA[p], saccA[p]);
            saccB[p] = ffma2(cfB, uhB[p], saccB[p]);
        }
    }

    float a0, a1, a2, a3;
    float* spA = g_sbuf[PASS] + (bA * NUM_CAPS + c) * DIM_VEC;
    float* spB = g_sbuf[PASS] + (bB * NUM_CAPS + c) * DIM_VEC;
    #pragma unroll
    for (int q = 0; q < 4; q++) {
        unpack2(saccA[2 * q], a0, a1); unpack2(saccA[2 * q + 1], a2, a3);
        asm volatile("red.global.add.v4.f32 [%0], {%1,%2,%3,%4};"
                     :: "l"(spA + 4 * q), "f"(a0), "f"(a1), "f"(a2), "f"(a3) : "memory");
        unpack2(saccB[2 * q], a0, a1); unpack2(saccB[2 * q + 1], a2, a3);
        asm volatile("red.global.add.v4.f32 [%0], {%1,%2,%3,%4};"
                     :: "l"(spB + 4 * q), "f"(a0), "f"(a1), "f"(a2), "f"(a3) : "memory");
    }
}

// out = squash(s2); re-zero all scratch for graph-replay determinism
__global__ void final_kernel(float* __restrict__ out)
{
    cudaTriggerProgrammaticLaunchCompletion();
    cudaGridDependencySynchronize();
    int t = blockIdx.x * blockDim.x + threadIdx.x;
    if (t < BATCH * NUM_CAPS) {
        float4* sp = (float4*)(g_sbuf[2] + t * DIM_VEC);
        float4 s4[4]; float sq = 0.f;
        #pragma unroll
        for (int q = 0; q < 4; q++) {
            s4[q] = sp[q];
            sq = fmaf(s4[q].x, s4[q].x, sq); sq = fmaf(s4[q].y, s4[q].y, sq);
            sq = fmaf(s4[q].z, s4[q].z, sq); sq = fmaf(s4[q].w, s4[q].w, sq);
        }
        float scale = sq / (1.f + sq) * rsqrtf(sq + EPS);
        float4* dst = (float4*)(out + t * DIM_VEC);
        float4 z = make_float4(0.f, 0.f, 0.f, 0.f);
        #pragma unroll
        for (int q = 0; q < 4; q++) {
            float4 o; o.x = scale * s4[q].x; o.y = scale * s4[q].y;
                      o.z = scale * s4[q].z; o.w = scale * s4[q].w;
            dst[q] = o;
            sp[q] = z;
        }
    }
    if (t < BATCH * NUM_CAPS * DIM_VEC) {
        g_sbuf[0][t] = 0.f;
        g_sbuf[1][t] = 0.f;
    }
}

extern "C" void kernel_launch(void* const* d_in, const int* in_sizes, int n_in,
                              void* d_out, int out_size)
{
    const float* x = nullptr; const float* W = nullptr; const float* bias = nullptr;
    for (int k = 0; k < n_in; k++) {
        if (in_sizes[k] == BATCH * IN_CAPS * 8)                    x    = (const float*)d_in[k];
        else if (in_sizes[k] == IN_CAPS * NUM_CAPS * DIM_VEC * 8)  W    = (const float*)d_in[k];
        else if (in_sizes[k] == IN_CAPS * NUM_CAPS)                bias = (const float*)d_in[k];
    }
    float* out = (float*)d_out;

    cudaFuncSetAttribute(pass0_kernel,   cudaFuncAttributeMaxDynamicSharedMemorySize, SMEM0_BYTES);
    cudaFuncSetAttribute(pass_kernel<1>, cudaFuncAttributeMaxDynamicSharedMemorySize, SMEM_BYTES);
    cudaFuncSetAttribute(pass_kernel<2>, cudaFuncAttributeMaxDynamicSharedMemorySize, SMEM_BYTES);

    cudaLaunchAttribute at[1];
    at[0].id = cudaLaunchAttributeProgrammaticStreamSerialization;
    at[0].val.programmaticStreamSerializationAllowed = 1;

    cudaLaunchConfig_t c0 = {};
    c0.gridDim = dim3(NBLK_I0, NBLK_B0);
    c0.blockDim = dim3(NTH, 1, 1);
    c0.dynamicSmemBytes = SMEM0_BYTES;
    c0.stream = 0;
    c0.attrs = at;
    c0.numAttrs = 1;
    cudaLaunchKernelEx(&c0, pass0_kernel, x, W, bias);

    cudaLaunchConfig_t cfg = {};
    cfg.gridDim = dim3(NBLK_I, NBLK_B);
    cfg.blockDim = dim3(NTH, 1, 1);
    cfg.dynamicSmemBytes = SMEM_BYTES;
    cfg.stream = 0;
    cfg.attrs = at;
    cfg.numAttrs = 1;
    cudaLaunchKernelEx(&cfg, pass_kernel<1>, x, W, bias);
    cudaLaunchKernelEx(&cfg, pass_kernel<2>, x, W, bias);

    cudaLaunchConfig_t fcfg = {};
    fcfg.gridDim = dim3((BATCH * NUM_CAPS * DIM_VEC + 255) / 256, 1, 1);
    fcfg.blockDim = dim3(256, 1, 1);
    fcfg.dynamicSmemBytes = 0;
    fcfg.stream = 0;
    fcfg.attrs = at;
    fcfg.numAttrs = 1;
    cudaLaunchKernelEx(&fcfg, final_kernel, out);
}